// round 1
// baseline (speedup 1.0000x reference)
#include <cuda_runtime.h>
#include <math.h>

// Problem constants (fixed shapes per reference)
#define NN      100000
#define EMAX    1700000
#define NHEADS  4
#define NHID    64
#define F1      256     // NHEADS*NHID
#define NCLASS  40
#define SB      512
#define NB1     ((NN + SB - 1) / SB)   // 196

// ---------------- scratch (static device globals; no allocation) ----------------
__device__ float g_Wcat[128 * 256];                 // W transposed/concatenated [K=128][N=256]
__device__ float g_Wh1[(size_t)NN * F1];            // layer1 Wh  [N,256]
__device__ float g_h  [(size_t)NN * F1];            // layer1 out [N,256]
__device__ float g_s1r[NN * 4];
__device__ float g_s1c[NN * 4];
__device__ float g_Wh2[(size_t)NN * NCLASS];        // layer2 Wh [N,40]
__device__ float g_s2r[NN];
__device__ float g_s2c[NN];
__device__ int   g_deg[NN];
__device__ int   g_cur[NN];
__device__ int   g_off[NN + 1];
__device__ int   g_csr[EMAX];
__device__ int   g_bsum[256];
__device__ int   g_boff[256];

// ---------------- helpers ----------------
union F2u { float2 f; unsigned long long u; };

__device__ __forceinline__ void ffma2(F2u& d, const F2u& a, const F2u& b) {
    // packed fp32 FMA (full-rate fp32 path on Blackwell)
    asm("fma.rn.f32x2 %0, %1, %2, %0;" : "+l"(d.u) : "l"(a.u), "l"(b.u));
}

__device__ __forceinline__ float wmax(float v) {
    #pragma unroll
    for (int o = 16; o; o >>= 1) v = fmaxf(v, __shfl_xor_sync(0xffffffffu, v, o));
    return v;
}
__device__ __forceinline__ float wsum(float v) {
    #pragma unroll
    for (int o = 16; o; o >>= 1) v += __shfl_xor_sync(0xffffffffu, v, o);
    return v;
}
__device__ __forceinline__ float lrelu(float v) { return v > 0.f ? v : 0.1f * v; }
__device__ __forceinline__ float elu(float v)   { return v > 0.f ? v : expm1f(v); }

// ---------------- small setup kernels ----------------
__global__ void k_zero() {
    int i = blockIdx.x * blockDim.x + threadIdx.x;
    if (i < NN) { g_deg[i] = 0; g_cur[i] = 0; }
}

// Wcat[k][h*64+c] = W[h][k][c]
__global__ void k_wcat(const float* __restrict__ W) {
    int idx = blockIdx.x * blockDim.x + threadIdx.x;   // 0..32767
    int k = idx >> 8, n = idx & 255;
    g_Wcat[idx] = W[(n >> 6) * (128 * 64) + k * 64 + (n & 63)];
}

// ---------------- CSR build ----------------
__global__ void k_count(const int* __restrict__ row, int E) {
    int e = blockIdx.x * blockDim.x + threadIdx.x;
    if (e < E) atomicAdd(&g_deg[__ldg(&row[e])], 1);
}

__global__ void k_scan1() {
    __shared__ int s[SB];
    int tid = threadIdx.x, g = blockIdx.x * SB + tid;
    int v = (g < NN) ? g_deg[g] : 0;
    s[tid] = v; __syncthreads();
    for (int o = 1; o < SB; o <<= 1) {
        int t = (tid >= o) ? s[tid - o] : 0;
        __syncthreads();
        s[tid] += t;
        __syncthreads();
    }
    if (g < NN) g_off[g] = s[tid] - v;           // exclusive within block
    if (tid == SB - 1) g_bsum[blockIdx.x] = s[tid];
}

__global__ void k_scan2() {
    __shared__ int s[256];
    int tid = threadIdx.x;
    int v = (tid < NB1) ? g_bsum[tid] : 0;
    s[tid] = v; __syncthreads();
    for (int o = 1; o < 256; o <<= 1) {
        int t = (tid >= o) ? s[tid - o] : 0;
        __syncthreads();
        s[tid] += t;
        __syncthreads();
    }
    g_boff[tid] = s[tid] - v;
}

__global__ void k_scan3(int E) {
    int tid = threadIdx.x, g = blockIdx.x * SB + tid;
    if (g < NN) g_off[g] += g_boff[blockIdx.x];
    if (g == 0) g_off[NN] = E;
}

__global__ void k_fill(const int* __restrict__ row, const int* __restrict__ col, int E) {
    int e = blockIdx.x * blockDim.x + threadIdx.x;
    if (e >= E) return;
    int r = __ldg(&row[e]);
    int p = g_off[r] + atomicAdd(&g_cur[r], 1);
    g_csr[p] = __ldg(&col[e]);
}

// ---------------- GEMM: C[M,N] = A[M,K] @ B[K,N], fp32, f32x2 packed ----------------
template<int BN, int TN>
__global__ __launch_bounds__(256)
void k_gemm(const float* __restrict__ A, const float* __restrict__ B,
            float* __restrict__ C, int M, int N, int K) {
    constexpr int BM = 128, BK = 32, TM = 8;
    constexpr int TX = BN / TN;   // 16 for both configs
    __shared__ float As[BK][BM + 4];
    __shared__ float Bs[BK][BN];

    int tid = threadIdx.x;
    int tx = tid % TX;
    int ty = tid / TX;
    int m0 = blockIdx.x * BM;
    int n0 = blockIdx.y * BN;

    F2u acc[TM][TN / 2];
    #pragma unroll
    for (int i = 0; i < TM; i++)
        #pragma unroll
        for (int p = 0; p < TN / 2; p++) acc[i][p].f = make_float2(0.f, 0.f);

    for (int kt = 0; kt < K; kt += BK) {
        // A tile: 128 rows x 32 k, coalesced float4, store transposed
        #pragma unroll
        for (int t = 0; t < 4; t++) {
            int idx = tid + t * 256;         // 0..1023
            int r   = idx >> 3;              // 0..127
            int kq  = (idx & 7) * 4;         // 0..28
            float4 av = make_float4(0.f, 0.f, 0.f, 0.f);
            if (m0 + r < M) av = *(const float4*)&A[(size_t)(m0 + r) * K + kt + kq];
            As[kq + 0][r] = av.x; As[kq + 1][r] = av.y;
            As[kq + 2][r] = av.z; As[kq + 3][r] = av.w;
        }
        // B tile: 32 k x BN cols
        #pragma unroll
        for (int t = 0; t < BN / 32; t++) {
            int idx = tid + t * 256;
            int k   = idx / (BN / 4);
            int nq  = (idx % (BN / 4)) * 4;
            float4 bv = make_float4(0.f, 0.f, 0.f, 0.f);
            if (n0 + nq < N) bv = *(const float4*)&B[(size_t)(kt + k) * N + n0 + nq];
            *(float4*)&Bs[k][nq] = bv;
        }
        __syncthreads();
        #pragma unroll
        for (int k = 0; k < BK; k++) {
            float4 a0 = *(const float4*)&As[k][ty * TM];
            float4 a1 = *(const float4*)&As[k][ty * TM + 4];
            float av[8] = {a0.x, a0.y, a0.z, a0.w, a1.x, a1.y, a1.z, a1.w};
            F2u bp[TN / 2];
            #pragma unroll
            for (int c = 0; c < TN / 4; c++) {
                float4 b = *(const float4*)&Bs[k][tx * TN + c * 4];
                bp[c * 2 + 0].f = make_float2(b.x, b.y);
                bp[c * 2 + 1].f = make_float2(b.z, b.w);
            }
            #pragma unroll
            for (int i = 0; i < TM; i++) {
                F2u ai; ai.f = make_float2(av[i], av[i]);
                #pragma unroll
                for (int p = 0; p < TN / 2; p++) ffma2(acc[i][p], ai, bp[p]);
            }
        }
        __syncthreads();
    }
    #pragma unroll
    for (int i = 0; i < TM; i++) {
        int gm = m0 + ty * TM + i;
        if (gm >= M) continue;
        #pragma unroll
        for (int c = 0; c < TN / 4; c++) {
            int gn = n0 + tx * TN + c * 4;
            if (gn >= N) continue;
            float4 o = make_float4(acc[i][c * 2].f.x, acc[i][c * 2].f.y,
                                   acc[i][c * 2 + 1].f.x, acc[i][c * 2 + 1].f.y);
            *(float4*)&C[(size_t)gm * N + gn] = o;
        }
    }
}

// ---------------- attention scalars ----------------
// layer1: warp per node; Wh1[i] dotted with a_src / a_dst per head
__global__ void k_s1(const float* __restrict__ a) {
    int gw = (blockIdx.x * blockDim.x + threadIdx.x) >> 5;
    int lane = threadIdx.x & 31;
    if (gw >= NN) return;
    const float* wp = &g_Wh1[(size_t)gw * F1];
    float sr[4] = {0.f, 0.f, 0.f, 0.f};
    float sc[4] = {0.f, 0.f, 0.f, 0.f};
    #pragma unroll
    for (int r = 0; r < 8; r++) {
        int h = r >> 1;
        int c = (r & 1) * 32 + lane;
        float w = __ldg(&wp[r * 32 + lane]);
        sr[h] += w * __ldg(&a[h * 128 + c]);
        sc[h] += w * __ldg(&a[h * 128 + 64 + c]);
    }
    #pragma unroll
    for (int h = 0; h < 4; h++) { sr[h] = wsum(sr[h]); sc[h] = wsum(sc[h]); }
    if (lane == 0) {
        *(float4*)&g_s1r[gw * 4] = make_float4(sr[0], sr[1], sr[2], sr[3]);
        *(float4*)&g_s1c[gw * 4] = make_float4(sc[0], sc[1], sc[2], sc[3]);
    }
}

__global__ void k_s2(const float* __restrict__ aout) {
    int gw = (blockIdx.x * blockDim.x + threadIdx.x) >> 5;
    int lane = threadIdx.x & 31;
    if (gw >= NN) return;
    const float* wp = &g_Wh2[(size_t)gw * NCLASS];
    float v0 = __ldg(&wp[lane]);
    float v1 = (lane < 8) ? __ldg(&wp[32 + lane]) : 0.f;
    float sr = v0 * __ldg(&aout[lane]) + ((lane < 8) ? v1 * __ldg(&aout[32 + lane]) : 0.f);
    float sc = v0 * __ldg(&aout[40 + lane]) + ((lane < 8) ? v1 * __ldg(&aout[72 + lane]) : 0.f);
    sr = wsum(sr); sc = wsum(sc);
    if (lane == 0) { g_s2r[gw] = sr; g_s2c[gw] = sc; }
}

// ---------------- layer1 attention aggregation (warp per destination node) ----------------
__global__ void k_gat1() {
    int gw = (blockIdx.x * blockDim.x + threadIdx.x) >> 5;
    int lane = threadIdx.x & 31;
    if (gw >= NN) return;
    const float4 sr = *(const float4*)&g_s1r[gw * 4];
    int beg = g_off[gw], end = g_off[gw + 1];

    // pass 1: segment max of leaky_relu(e) per head
    float m0 = -1e30f, m1 = -1e30f, m2 = -1e30f, m3 = -1e30f;
    for (int e = beg + lane; e < end; e += 32) {
        int j = __ldg(&g_csr[e]);
        float4 sc = __ldg((const float4*)&g_s1c[j * 4]);
        m0 = fmaxf(m0, lrelu(sr.x + sc.x));
        m1 = fmaxf(m1, lrelu(sr.y + sc.y));
        m2 = fmaxf(m2, lrelu(sr.z + sc.z));
        m3 = fmaxf(m3, lrelu(sr.w + sc.w));
    }
    m0 = wmax(m0); m1 = wmax(m1); m2 = wmax(m2); m3 = wmax(m3);

    // pass 2: denominator + weighted aggregation (denominator redundantly per lane)
    float acc[8] = {0.f, 0.f, 0.f, 0.f, 0.f, 0.f, 0.f, 0.f};
    float d0 = 0.f, d1 = 0.f, d2 = 0.f, d3 = 0.f;
    int j = 0; float4 sc = make_float4(0, 0, 0, 0);
    if (beg < end) { j = __ldg(&g_csr[beg]); sc = __ldg((const float4*)&g_s1c[j * 4]); }
    for (int e = beg; e < end; e++) {
        int jn = 0; float4 scn = make_float4(0, 0, 0, 0);
        if (e + 1 < end) { jn = __ldg(&g_csr[e + 1]); scn = __ldg((const float4*)&g_s1c[jn * 4]); }
        float e0 = __expf(lrelu(sr.x + sc.x) - m0); d0 += e0;
        float e1 = __expf(lrelu(sr.y + sc.y) - m1); d1 += e1;
        float e2 = __expf(lrelu(sr.z + sc.z) - m2); d2 += e2;
        float e3 = __expf(lrelu(sr.w + sc.w) - m3); d3 += e3;
        const float* wp = &g_Wh1[(size_t)j * F1];
        acc[0] += e0 * __ldg(&wp[        lane]);
        acc[1] += e0 * __ldg(&wp[ 32  +  lane]);
        acc[2] += e1 * __ldg(&wp[ 64  +  lane]);
        acc[3] += e1 * __ldg(&wp[ 96  +  lane]);
        acc[4] += e2 * __ldg(&wp[128  +  lane]);
        acc[5] += e2 * __ldg(&wp[160  +  lane]);
        acc[6] += e3 * __ldg(&wp[192  +  lane]);
        acc[7] += e3 * __ldg(&wp[224  +  lane]);
        j = jn; sc = scn;
    }
    float inv[4] = {1.f / d0, 1.f / d1, 1.f / d2, 1.f / d3};
    float* op = &g_h[(size_t)gw * F1];
    #pragma unroll
    for (int r = 0; r < 8; r++)
        op[r * 32 + lane] = elu(acc[r] * inv[r >> 1]);
}

// ---------------- layer2 attention + ELU + log_softmax (warp per node) ----------------
__global__ void k_gat2(float* __restrict__ out) {
    int gw = (blockIdx.x * blockDim.x + threadIdx.x) >> 5;
    int lane = threadIdx.x & 31;
    if (gw >= NN) return;
    float s2 = __ldg(&g_s2r[gw]);
    int beg = g_off[gw], end = g_off[gw + 1];

    float m = -1e30f;
    for (int e = beg + lane; e < end; e += 32) {
        int j = __ldg(&g_csr[e]);
        m = fmaxf(m, lrelu(s2 + __ldg(&g_s2c[j])));
    }
    m = wmax(m);

    float a0 = 0.f, a1 = 0.f, den = 0.f;
    int j = 0; float scj = 0.f;
    if (beg < end) { j = __ldg(&g_csr[beg]); scj = __ldg(&g_s2c[j]); }
    for (int e = beg; e < end; e++) {
        int jn = 0; float scn = 0.f;
        if (e + 1 < end) { jn = __ldg(&g_csr[e + 1]); scn = __ldg(&g_s2c[jn]); }
        float ex = __expf(lrelu(s2 + scj) - m);
        den += ex;
        const float* wp = &g_Wh2[(size_t)j * NCLASS];
        a0 += ex * __ldg(&wp[lane]);
        if (lane < 8) a1 += ex * __ldg(&wp[32 + lane]);
        j = jn; scj = scn;
    }
    float inv = 1.f / den;
    float o0 = elu(a0 * inv);
    float o1 = (lane < 8) ? elu(a1 * inv) : -1e30f;
    // log_softmax over 40 classes
    float mm = wmax(fmaxf(o0, o1));
    float se = __expf(o0 - mm) + ((lane < 8) ? __expf(o1 - mm) : 0.f);
    se = wsum(se);
    float L = mm + logf(se);
    float* op = &out[(size_t)gw * NCLASS];
    op[lane] = o0 - L;
    if (lane < 8) op[32 + lane] = o1 - L;
}

// ---------------- launch ----------------
extern "C" void kernel_launch(void* const* d_in, const int* in_sizes, int n_in,
                              void* d_out, int out_size) {
    const float* x    = (const float*)d_in[0];
    const float* W    = (const float*)d_in[1];
    const float* a    = (const float*)d_in[2];
    const float* Wout = (const float*)d_in[3];
    const float* aout = (const float*)d_in[4];
    const int*   row  = (const int*)d_in[5];
    const int*   col  = (const int*)d_in[6];
    int E = in_sizes[5];
    float* out = (float*)d_out;

    void *pWcat, *pWh1, *ph, *pWh2;
    cudaGetSymbolAddress(&pWcat, g_Wcat);
    cudaGetSymbolAddress(&pWh1,  g_Wh1);
    cudaGetSymbolAddress(&ph,    g_h);
    cudaGetSymbolAddress(&pWh2,  g_Wh2);

    // CSR build (independent of GEMMs, but stream-serial is fine)
    k_zero<<<(NN + 255) / 256, 256>>>();
    k_wcat<<<128, 256>>>(W);
    k_count<<<(E + 255) / 256, 256>>>(row, E);
    k_scan1<<<NB1, SB>>>();
    k_scan2<<<1, 256>>>();
    k_scan3<<<NB1, SB>>>(E);
    k_fill<<<(E + 255) / 256, 256>>>(row, col, E);

    // layer 1
    k_gemm<128, 8><<<dim3((NN + 127) / 128, 2), 256>>>(x, (const float*)pWcat, (float*)pWh1, NN, 256, 128);
    k_s1<<<(NN + 7) / 8, 256>>>(a);
    k_gat1<<<(NN + 7) / 8, 256>>>();

    // layer 2
    k_gemm<64, 4><<<dim3((NN + 127) / 128, 1), 256>>>((const float*)ph, Wout, (float*)pWh2, NN, 40, 256);
    k_s2<<<(NN + 7) / 8, 256>>>(aout);
    k_gat2<<<(NN + 7) / 8, 256>>>(out);
}

// round 2
// speedup vs baseline: 1.0191x; 1.0191x over previous
#include <cuda_runtime.h>
#include <math.h>

// Problem constants (fixed shapes per reference)
#define NN      100000
#define EMAX    1700000
#define NHEADS  4
#define NHID    64
#define F1      256     // NHEADS*NHID
#define NCLASS  40
#define SB      512
#define NB1     ((NN + SB - 1) / SB)   // 196

// ---------------- scratch (static device globals; no allocation) ----------------
__device__ float g_Wcat[128 * 256];                 // W transposed/concatenated [K=128][N=256]
__device__ float g_Wh1[(size_t)NN * F1];            // layer1 Wh  [N,256]
__device__ float g_h  [(size_t)NN * F1];            // layer1 out [N,256]
__device__ float g_s1r[NN * 4];
__device__ float g_s1c[NN * 4];
__device__ float g_Wh2[(size_t)NN * NCLASS];        // layer2 Wh [N,40]
__device__ float g_s2r[NN];
__device__ float g_s2c[NN];
__device__ int   g_deg[NN];
__device__ int   g_cur[NN];
__device__ int   g_off[NN + 1];
__device__ int   g_csr[EMAX];
__device__ int   g_bsum[256];
__device__ int   g_boff[256];

// ---------------- helpers ----------------
union F2u { float2 f; unsigned long long u; };

__device__ __forceinline__ void ffma2(F2u& d, const F2u& a, const F2u& b) {
    asm("fma.rn.f32x2 %0, %1, %2, %0;" : "+l"(d.u) : "l"(a.u), "l"(b.u));
}

__device__ __forceinline__ float wmax(float v) {
    #pragma unroll
    for (int o = 16; o; o >>= 1) v = fmaxf(v, __shfl_xor_sync(0xffffffffu, v, o));
    return v;
}
__device__ __forceinline__ float wsum(float v) {
    #pragma unroll
    for (int o = 16; o; o >>= 1) v += __shfl_xor_sync(0xffffffffu, v, o);
    return v;
}
__device__ __forceinline__ float lrelu(float v) { return v > 0.f ? v : 0.1f * v; }
__device__ __forceinline__ float elu(float v)   { return v > 0.f ? v : expm1f(v); }

// ---------------- small setup kernels ----------------
__global__ void k_zero() {
    int i = blockIdx.x * blockDim.x + threadIdx.x;
    if (i < NN) { g_deg[i] = 0; g_cur[i] = 0; }
}

// Wcat[k][h*64+c] = W[h][k][c]
__global__ void k_wcat(const float* __restrict__ W) {
    int idx = blockIdx.x * blockDim.x + threadIdx.x;   // 0..32767
    int k = idx >> 8, n = idx & 255;
    g_Wcat[idx] = W[(n >> 6) * (128 * 64) + k * 64 + (n & 63)];
}

// ---------------- CSR build ----------------
__global__ void k_count(const int* __restrict__ row, int E) {
    int e = blockIdx.x * blockDim.x + threadIdx.x;
    if (e < E) atomicAdd(&g_deg[__ldg(&row[e])], 1);
}

__global__ void k_scan1() {
    __shared__ int s[SB];
    int tid = threadIdx.x, g = blockIdx.x * SB + tid;
    int v = (g < NN) ? g_deg[g] : 0;
    s[tid] = v; __syncthreads();
    for (int o = 1; o < SB; o <<= 1) {
        int t = (tid >= o) ? s[tid - o] : 0;
        __syncthreads();
        s[tid] += t;
        __syncthreads();
    }
    if (g < NN) g_off[g] = s[tid] - v;           // exclusive within block
    if (tid == SB - 1) g_bsum[blockIdx.x] = s[tid];
}

__global__ void k_scan2() {
    __shared__ int s[256];
    int tid = threadIdx.x;
    int v = (tid < NB1) ? g_bsum[tid] : 0;
    s[tid] = v; __syncthreads();
    for (int o = 1; o < 256; o <<= 1) {
        int t = (tid >= o) ? s[tid - o] : 0;
        __syncthreads();
        s[tid] += t;
        __syncthreads();
    }
    g_boff[tid] = s[tid] - v;
}

__global__ void k_scan3(int E) {
    int tid = threadIdx.x, g = blockIdx.x * SB + tid;
    if (g < NN) g_off[g] += g_boff[blockIdx.x];
    if (g == 0) g_off[NN] = E;
}

__global__ void k_fill(const int* __restrict__ row, const int* __restrict__ col, int E) {
    int e = blockIdx.x * blockDim.x + threadIdx.x;
    if (e >= E) return;
    int r = __ldg(&row[e]);
    int p = g_off[r] + atomicAdd(&g_cur[r], 1);
    g_csr[p] = __ldg(&col[e]);
}

// ---------------- GEMM: C[M,N] = A[M,K] @ B[K,N], fp32, f32x2 packed ----------------
template<int BN, int TN>
__global__ __launch_bounds__(256)
void k_gemm(const float* __restrict__ A, const float* __restrict__ B,
            float* __restrict__ C, int M, int N, int K) {
    constexpr int BM = 128, BK = 32, TM = 8;
    constexpr int TX = BN / TN;   // 16 for both configs
    __shared__ float As[BK][BM + 4];
    __shared__ float Bs[BK][BN];

    int tid = threadIdx.x;
    int tx = tid % TX;
    int ty = tid / TX;
    int m0 = blockIdx.x * BM;
    int n0 = blockIdx.y * BN;

    F2u acc[TM][TN / 2];
    #pragma unroll
    for (int i = 0; i < TM; i++)
        #pragma unroll
        for (int p = 0; p < TN / 2; p++) acc[i][p].f = make_float2(0.f, 0.f);

    for (int kt = 0; kt < K; kt += BK) {
        #pragma unroll
        for (int t = 0; t < 4; t++) {
            int idx = tid + t * 256;         // 0..1023
            int r   = idx >> 3;              // 0..127
            int kq  = (idx & 7) * 4;         // 0..28
            float4 av = make_float4(0.f, 0.f, 0.f, 0.f);
            if (m0 + r < M) av = *(const float4*)&A[(size_t)(m0 + r) * K + kt + kq];
            As[kq + 0][r] = av.x; As[kq + 1][r] = av.y;
            As[kq + 2][r] = av.z; As[kq + 3][r] = av.w;
        }
        #pragma unroll
        for (int t = 0; t < BN / 32; t++) {
            int idx = tid + t * 256;
            int k   = idx / (BN / 4);
            int nq  = (idx % (BN / 4)) * 4;
            float4 bv = make_float4(0.f, 0.f, 0.f, 0.f);
            if (n0 + nq < N) bv = *(const float4*)&B[(size_t)(kt + k) * N + n0 + nq];
            *(float4*)&Bs[k][nq] = bv;
        }
        __syncthreads();
        #pragma unroll
        for (int k = 0; k < BK; k++) {
            float4 a0 = *(const float4*)&As[k][ty * TM];
            float4 a1 = *(const float4*)&As[k][ty * TM + 4];
            float av[8] = {a0.x, a0.y, a0.z, a0.w, a1.x, a1.y, a1.z, a1.w};
            F2u bp[TN / 2];
            #pragma unroll
            for (int c = 0; c < TN / 4; c++) {
                float4 b = *(const float4*)&Bs[k][tx * TN + c * 4];
                bp[c * 2 + 0].f = make_float2(b.x, b.y);
                bp[c * 2 + 1].f = make_float2(b.z, b.w);
            }
            #pragma unroll
            for (int i = 0; i < TM; i++) {
                F2u ai; ai.f = make_float2(av[i], av[i]);
                #pragma unroll
                for (int p = 0; p < TN / 2; p++) ffma2(acc[i][p], ai, bp[p]);
            }
        }
        __syncthreads();
    }
    #pragma unroll
    for (int i = 0; i < TM; i++) {
        int gm = m0 + ty * TM + i;
        if (gm >= M) continue;
        #pragma unroll
        for (int c = 0; c < TN / 4; c++) {
            int gn = n0 + tx * TN + c * 4;
            if (gn >= N) continue;
            float4 o = make_float4(acc[i][c * 2].f.x, acc[i][c * 2].f.y,
                                   acc[i][c * 2 + 1].f.x, acc[i][c * 2 + 1].f.y);
            *(float4*)&C[(size_t)gm * N + gn] = o;
        }
    }
}

// ---------------- attention scalars ----------------
__global__ void k_s1(const float* __restrict__ a) {
    int gw = (blockIdx.x * blockDim.x + threadIdx.x) >> 5;
    int lane = threadIdx.x & 31;
    if (gw >= NN) return;
    const float* wp = &g_Wh1[(size_t)gw * F1];
    float sr[4] = {0.f, 0.f, 0.f, 0.f};
    float sc[4] = {0.f, 0.f, 0.f, 0.f};
    #pragma unroll
    for (int r = 0; r < 8; r++) {
        int h = r >> 1;
        int c = (r & 1) * 32 + lane;
        float w = __ldg(&wp[r * 32 + lane]);
        sr[h] += w * __ldg(&a[h * 128 + c]);
        sc[h] += w * __ldg(&a[h * 128 + 64 + c]);
    }
    #pragma unroll
    for (int h = 0; h < 4; h++) { sr[h] = wsum(sr[h]); sc[h] = wsum(sc[h]); }
    if (lane == 0) {
        *(float4*)&g_s1r[gw * 4] = make_float4(sr[0], sr[1], sr[2], sr[3]);
        *(float4*)&g_s1c[gw * 4] = make_float4(sc[0], sc[1], sc[2], sc[3]);
    }
}

__global__ void k_s2(const float* __restrict__ aout) {
    int gw = (blockIdx.x * blockDim.x + threadIdx.x) >> 5;
    int lane = threadIdx.x & 31;
    if (gw >= NN) return;
    const float* wp = &g_Wh2[(size_t)gw * NCLASS];
    float v0 = __ldg(&wp[lane]);
    float v1 = (lane < 8) ? __ldg(&wp[32 + lane]) : 0.f;
    float sr = v0 * __ldg(&aout[lane]) + ((lane < 8) ? v1 * __ldg(&aout[32 + lane]) : 0.f);
    float sc = v0 * __ldg(&aout[40 + lane]) + ((lane < 8) ? v1 * __ldg(&aout[72 + lane]) : 0.f);
    sr = wsum(sr); sc = wsum(sc);
    if (lane == 0) { g_s2r[gw] = sr; g_s2c[gw] = sc; }
}

// ---------------- layer1 attention aggregation (warp per destination node) ----------------
// Single pass: softmax WITHOUT max-subtraction (|e| <= ~10, exp safe in fp32).
// 32 edges per step: exp computed lane-parallel, aggregation via shfl broadcast.
__global__ void k_gat1() {
    int gw = (blockIdx.x * blockDim.x + threadIdx.x) >> 5;
    int lane = threadIdx.x & 31;
    if (gw >= NN) return;
    const float4 sr = *(const float4*)&g_s1r[gw * 4];
    int beg = g_off[gw], end = g_off[gw + 1];

    float acc[8] = {0.f, 0.f, 0.f, 0.f, 0.f, 0.f, 0.f, 0.f};
    float d0 = 0.f, d1 = 0.f, d2 = 0.f, d3 = 0.f;

    for (int base = beg; base < end; base += 32) {
        int e = base + lane;
        int j = 0;
        float ex0 = 0.f, ex1 = 0.f, ex2 = 0.f, ex3 = 0.f;
        if (e < end) {
            j = __ldg(&g_csr[e]);
            float4 sc = __ldg((const float4*)&g_s1c[j * 4]);
            ex0 = __expf(lrelu(sr.x + sc.x));
            ex1 = __expf(lrelu(sr.y + sc.y));
            ex2 = __expf(lrelu(sr.z + sc.z));
            ex3 = __expf(lrelu(sr.w + sc.w));
            d0 += ex0; d1 += ex1; d2 += ex2; d3 += ex3;
        }
        int cnt = min(32, end - base);
        for (int k = 0; k < cnt; k++) {
            int   jj = __shfl_sync(0xffffffffu, j,   k);
            float w0 = __shfl_sync(0xffffffffu, ex0, k);
            float w1 = __shfl_sync(0xffffffffu, ex1, k);
            float w2 = __shfl_sync(0xffffffffu, ex2, k);
            float w3 = __shfl_sync(0xffffffffu, ex3, k);
            const float* wp = &g_Wh1[(size_t)jj * F1];
            acc[0] += w0 * __ldg(&wp[        lane]);
            acc[1] += w0 * __ldg(&wp[ 32  +  lane]);
            acc[2] += w1 * __ldg(&wp[ 64  +  lane]);
            acc[3] += w1 * __ldg(&wp[ 96  +  lane]);
            acc[4] += w2 * __ldg(&wp[128  +  lane]);
            acc[5] += w2 * __ldg(&wp[160  +  lane]);
            acc[6] += w3 * __ldg(&wp[192  +  lane]);
            acc[7] += w3 * __ldg(&wp[224  +  lane]);
        }
    }
    d0 = wsum(d0); d1 = wsum(d1); d2 = wsum(d2); d3 = wsum(d3);
    float inv[4] = {1.f / d0, 1.f / d1, 1.f / d2, 1.f / d3};
    float* op = &g_h[(size_t)gw * F1];
    #pragma unroll
    for (int r = 0; r < 8; r++)
        op[r * 32 + lane] = elu(acc[r] * inv[r >> 1]);
}

// ---------------- layer2 attention + ELU + log_softmax (warp per node) ----------------
__global__ void k_gat2(float* __restrict__ out) {
    int gw = (blockIdx.x * blockDim.x + threadIdx.x) >> 5;
    int lane = threadIdx.x & 31;
    if (gw >= NN) return;
    float s2v = __ldg(&g_s2r[gw]);
    int beg = g_off[gw], end = g_off[gw + 1];

    float a0 = 0.f, a1 = 0.f, den = 0.f;
    for (int base = beg; base < end; base += 32) {
        int e = base + lane;
        int j = 0; float ex = 0.f;
        if (e < end) {
            j = __ldg(&g_csr[e]);
            ex = __expf(lrelu(s2v + __ldg(&g_s2c[j])));
            den += ex;
        }
        int cnt = min(32, end - base);
        for (int k = 0; k < cnt; k++) {
            int   jj = __shfl_sync(0xffffffffu, j,  k);
            float w  = __shfl_sync(0xffffffffu, ex, k);
            const float* wp = &g_Wh2[(size_t)jj * NCLASS];
            a0 += w * __ldg(&wp[lane]);
            if (lane < 8) a1 += w * __ldg(&wp[32 + lane]);
        }
    }
    den = wsum(den);
    float inv = 1.f / den;
    float o0 = elu(a0 * inv);
    float o1 = (lane < 8) ? elu(a1 * inv) : -1e30f;
    // log_softmax over 40 classes (keep max for stability here)
    float mm = wmax(fmaxf(o0, o1));
    float se = __expf(o0 - mm) + ((lane < 8) ? __expf(o1 - mm) : 0.f);
    se = wsum(se);
    float L = mm + logf(se);
    float* op = &out[(size_t)gw * NCLASS];
    op[lane] = o0 - L;
    if (lane < 8) op[32 + lane] = o1 - L;
}

// ---------------- launch ----------------
extern "C" void kernel_launch(void* const* d_in, const int* in_sizes, int n_in,
                              void* d_out, int out_size) {
    const float* x    = (const float*)d_in[0];
    const float* W    = (const float*)d_in[1];
    const float* a    = (const float*)d_in[2];
    const float* Wout = (const float*)d_in[3];
    const float* aout = (const float*)d_in[4];
    const int*   row  = (const int*)d_in[5];
    const int*   col  = (const int*)d_in[6];
    int E = in_sizes[5];
    float* out = (float*)d_out;

    void *pWcat, *pWh1, *ph, *pWh2;
    cudaGetSymbolAddress(&pWcat, g_Wcat);
    cudaGetSymbolAddress(&pWh1,  g_Wh1);
    cudaGetSymbolAddress(&ph,    g_h);
    cudaGetSymbolAddress(&pWh2,  g_Wh2);

    // Side stream + events for overlapping the CSR build with GEMM1/s1.
    // Created lazily on the (uncaptured) correctness call; reused under capture.
    static cudaStream_t s2 = nullptr;
    static cudaEvent_t evF = nullptr, evJ = nullptr;
    if (!s2) {
        cudaStreamCreateWithFlags(&s2, cudaStreamNonBlocking);
        cudaEventCreateWithFlags(&evF, cudaEventDisableTiming);
        cudaEventCreateWithFlags(&evJ, cudaEventDisableTiming);
    }

    // 1: weight transpose (main)
    k_wcat<<<128, 256>>>(W);

    // fork CSR chain onto s2
    cudaEventRecord(evF, 0);
    cudaStreamWaitEvent(s2, evF, 0);

    k_zero <<<(NN + 255) / 256, 256, 0, s2>>>();           // 2
    k_count<<<(E + 255) / 256, 256, 0, s2>>>(row, E);      // 3

    // 4: GEMM1 on main (profiled slot)
    k_gemm<128, 8><<<dim3((NN + 127) / 128, 2), 256>>>(x, (const float*)pWcat, (float*)pWh1, NN, 256, 128);

    k_scan1<<<NB1, SB, 0, s2>>>();                         // 5
    k_scan2<<<1, 256, 0, s2>>>();                          // 6
    k_scan3<<<NB1, SB, 0, s2>>>(E);                        // 7
    k_fill <<<(E + 255) / 256, 256, 0, s2>>>(row, col, E); // 8

    k_s1<<<(NN + 7) / 8, 256>>>(a);                        // 9 (main)

    // join: gat1 needs both CSR (s2) and Wh1/s1 (main)
    cudaEventRecord(evJ, s2);
    cudaStreamWaitEvent(0, evJ, 0);

    k_gat1<<<(NN + 7) / 8, 256>>>();                       // 10

    // layer 2
    k_gemm<64, 4><<<dim3((NN + 127) / 128, 1), 256>>>((const float*)ph, Wout, (float*)pWh2, NN, 40, 256);
    k_s2<<<(NN + 7) / 8, 256>>>(aout);
    k_gat2<<<(NN + 7) / 8, 256>>>(out);
}

// round 4
// speedup vs baseline: 1.2369x; 1.2137x over previous
#include <cuda_runtime.h>
#include <cuda_bf16.h>
#include <mma.h>
#include <math.h>
#include <stdint.h>

using namespace nvcuda;

// Problem constants
#define NN      100000
#define EMAX    1700000
#define NCLASS  40
#define SB      512
#define NB1     ((NN + SB - 1) / SB)
#define NTILE   782                    // ceil(NN/128)
#define NPAD    (NTILE * 128)          // 100096

// ---------------- scratch (static device globals) ----------------
__device__ float g_Wh1[(size_t)NPAD * 256];   // layer1 Wh fp32 (padded rows zero)
__device__ float g_h  [(size_t)NPAD * 256];   // layer1 output (padded rows stay zero-init)
__device__ float g_Wh2[(size_t)NPAD * 48];    // layer2 Wh fp32, ld=48 (cols 40..47 zero)
__device__ float g_s1r[NN * 4];
__device__ float g_s1c[NN * 4];
__device__ float g_s2r[NN];
__device__ float g_s2c[NN];
__device__ int   g_deg[NN];
__device__ int   g_cur[NN];
__device__ int   g_off[NN + 1];
__device__ int   g_csr[EMAX];
__device__ int   g_bsum[256];
__device__ int   g_boff[256];
// pre-split bf16 weights, plain row-major
__device__ __align__(16) unsigned char g_B1h[128 * 256 * 2];  // B1[k][n], k<128, n<256
__device__ __align__(16) unsigned char g_B1l[128 * 256 * 2];
__device__ __align__(16) unsigned char g_B2h[256 * 48 * 2];   // B2[k][n], k<256, n<48 (n>=40 zero)
__device__ __align__(16) unsigned char g_B2l[256 * 48 * 2];

// ---------------- helpers ----------------
__device__ __forceinline__ float wmax(float v) {
    #pragma unroll
    for (int o = 16; o; o >>= 1) v = fmaxf(v, __shfl_xor_sync(0xffffffffu, v, o));
    return v;
}
__device__ __forceinline__ float wsum(float v) {
    #pragma unroll
    for (int o = 16; o; o >>= 1) v += __shfl_xor_sync(0xffffffffu, v, o);
    return v;
}
__device__ __forceinline__ float lrelu(float v) { return v > 0.f ? v : 0.1f * v; }
__device__ __forceinline__ float elu(float v)   { return v > 0.f ? v : expm1f(v); }

__device__ __forceinline__ void split4(float4 v, uint2& hi, uint2& lo) {
    __nv_bfloat16 h0 = __float2bfloat16_rn(v.x), h1 = __float2bfloat16_rn(v.y),
                  h2 = __float2bfloat16_rn(v.z), h3 = __float2bfloat16_rn(v.w);
    hi.x = ((uint32_t)__bfloat16_as_ushort(h1) << 16) | __bfloat16_as_ushort(h0);
    hi.y = ((uint32_t)__bfloat16_as_ushort(h3) << 16) | __bfloat16_as_ushort(h2);
    __nv_bfloat162 l01 = __floats2bfloat162_rn(v.x - __bfloat162float(h0), v.y - __bfloat162float(h1));
    __nv_bfloat162 l23 = __floats2bfloat162_rn(v.z - __bfloat162float(h2), v.w - __bfloat162float(h3));
    lo.x = *(uint32_t*)&l01;
    lo.y = *(uint32_t*)&l23;
}

// ---------------- prep: weights -> split bf16 ----------------
__global__ void k_prep(const float* __restrict__ W, const float* __restrict__ Wout) {
    for (int i = blockIdx.x * blockDim.x + threadIdx.x; i < 45056; i += gridDim.x * blockDim.x) {
        if (i < 32768) {                    // B1[k][n] = W[n/64][k][n%64]
            int k = i >> 8, n = i & 255;
            float v = W[(n >> 6) * 8192 + k * 64 + (n & 63)];
            __nv_bfloat16 h = __float2bfloat16_rn(v);
            __nv_bfloat16 l = __float2bfloat16_rn(v - __bfloat162float(h));
            *(__nv_bfloat16*)(g_B1h + i * 2) = h;
            *(__nv_bfloat16*)(g_B1l + i * 2) = l;
        } else {                            // B2[k][n] = Wout[k][n], n<40 else 0
            int j = i - 32768;
            int k = j / 48, n = j - k * 48;
            float v = (n < NCLASS) ? Wout[k * NCLASS + n] : 0.f;
            __nv_bfloat16 h = __float2bfloat16_rn(v);
            __nv_bfloat16 l = __float2bfloat16_rn(v - __bfloat162float(h));
            *(__nv_bfloat16*)(g_B2h + j * 2) = h;
            *(__nv_bfloat16*)(g_B2l + j * 2) = l;
        }
    }
}

// ---------------- CSR build ----------------
__global__ void k_zero() {
    int i = blockIdx.x * blockDim.x + threadIdx.x;
    if (i < NN) { g_deg[i] = 0; g_cur[i] = 0; }
}
__global__ void k_count(const int* __restrict__ row, int E) {
    int e = blockIdx.x * blockDim.x + threadIdx.x;
    if (e < E) atomicAdd(&g_deg[__ldg(&row[e])], 1);
}
__global__ void k_scan1() {
    __shared__ int s[SB];
    int tid = threadIdx.x, g = blockIdx.x * SB + tid;
    int v = (g < NN) ? g_deg[g] : 0;
    s[tid] = v; __syncthreads();
    for (int o = 1; o < SB; o <<= 1) {
        int t = (tid >= o) ? s[tid - o] : 0;
        __syncthreads(); s[tid] += t; __syncthreads();
    }
    if (g < NN) g_off[g] = s[tid] - v;
    if (tid == SB - 1) g_bsum[blockIdx.x] = s[tid];
}
__global__ void k_scan2() {
    __shared__ int s[256];
    int tid = threadIdx.x;
    int v = (tid < NB1) ? g_bsum[tid] : 0;
    s[tid] = v; __syncthreads();
    for (int o = 1; o < 256; o <<= 1) {
        int t = (tid >= o) ? s[tid - o] : 0;
        __syncthreads(); s[tid] += t; __syncthreads();
    }
    g_boff[tid] = s[tid] - v;
}
__global__ void k_scan3(int E) {
    int tid = threadIdx.x, g = blockIdx.x * SB + tid;
    if (g < NN) g_off[g] += g_boff[blockIdx.x];
    if (g == 0) g_off[NN] = E;
}
__global__ void k_fill(const int* __restrict__ row, const int* __restrict__ col, int E) {
    int e = blockIdx.x * blockDim.x + threadIdx.x;
    if (e >= E) return;
    int r = __ldg(&row[e]);
    int p = g_off[r] + atomicAdd(&g_cur[r], 1);
    g_csr[p] = __ldg(&col[e]);
}

// ---------------- GEMM1 (WMMA bf16 split): Wh1 = x @ B1  [128x256 per CTA, K=128] ----------------
#define G1_AH 0
#define G1_AL 34816
#define G1_BH 69632
#define G1_BL 137216
#define G1_BYTES 204800
// A ld = 136 (bf16), B ld = 264 (bf16)

__global__ __launch_bounds__(256) void k_gemm1(const float* __restrict__ x) {
    extern __shared__ __align__(16) unsigned char smem[];
    int tid = threadIdx.x;
    int m0 = blockIdx.x * 128;

    // B copy (hi+lo): 4096 uint4 each
    #pragma unroll
    for (int t = 0; t < 16; t++) {
        int i = tid + t * 256;
        int r = i >> 5, c = (i & 31) * 16;
        *(uint4*)(smem + G1_BH + r * 528 + c) = *(const uint4*)(g_B1h + r * 512 + c);
        *(uint4*)(smem + G1_BL + r * 528 + c) = *(const uint4*)(g_B1l + r * 512 + c);
    }
    // A load fp32 + split
    #pragma unroll
    for (int t = 0; t < 16; t++) {
        int i = tid + t * 256;               // 0..4095
        int r = i >> 5, kq = (i & 31) * 4;
        int gr = m0 + r;
        float4 v = make_float4(0.f, 0.f, 0.f, 0.f);
        if (gr < NN) v = __ldg((const float4*)&x[(size_t)gr * 128 + kq]);
        uint2 hi, lo;
        split4(v, hi, lo);
        *(uint2*)(smem + G1_AH + (r * 136 + kq) * 2) = hi;
        *(uint2*)(smem + G1_AL + (r * 136 + kq) * 2) = lo;
    }
    __syncthreads();

    int wid = tid >> 5;
    int wm = wid & 1, wn = wid >> 1;          // warp tile 64x64: 2 (M) x 4 (N)

    wmma::fragment<wmma::accumulator, 16, 16, 16, float> acc[4][4];
    #pragma unroll
    for (int i = 0; i < 4; i++)
        #pragma unroll
        for (int j = 0; j < 4; j++) wmma::fill_fragment(acc[i][j], 0.f);

    for (int pass = 0; pass < 3; pass++) {
        const __nv_bfloat16* A_ = (const __nv_bfloat16*)(smem + (pass == 2 ? G1_AL : G1_AH));
        const __nv_bfloat16* B_ = (const __nv_bfloat16*)(smem + (pass == 1 ? G1_BL : G1_BH));
        #pragma unroll
        for (int k8 = 0; k8 < 8; k8++) {
            wmma::fragment<wmma::matrix_a, 16, 16, 16, __nv_bfloat16, wmma::row_major> af[4];
            wmma::fragment<wmma::matrix_b, 16, 16, 16, __nv_bfloat16, wmma::row_major> bfr[4];
            #pragma unroll
            for (int i = 0; i < 4; i++)
                wmma::load_matrix_sync(af[i], A_ + (wm * 64 + i * 16) * 136 + k8 * 16, 136);
            #pragma unroll
            for (int j = 0; j < 4; j++)
                wmma::load_matrix_sync(bfr[j], B_ + (k8 * 16) * 264 + wn * 64 + j * 16, 264);
            #pragma unroll
            for (int i = 0; i < 4; i++)
                #pragma unroll
                for (int j = 0; j < 4; j++)
                    wmma::mma_sync(acc[i][j], af[i], bfr[j], acc[i][j]);
        }
    }
    #pragma unroll
    for (int i = 0; i < 4; i++)
        #pragma unroll
        for (int j = 0; j < 4; j++)
            wmma::store_matrix_sync(&g_Wh1[(size_t)(m0 + wm * 64 + i * 16) * 256 + wn * 64 + j * 16],
                                    acc[i][j], 256, wmma::mem_row_major);
}

// ---------------- GEMM2 (WMMA bf16 split): Wh2 = h @ B2  [128x48 per CTA, K=256] ----------------
#define G2_AH 0
#define G2_AL 67584
#define G2_BH 135168
#define G2_BL 163840
#define G2_BYTES 192512
// A ld = 264, B ld = 56

__global__ __launch_bounds__(256) void k_gemm2() {
    extern __shared__ __align__(16) unsigned char smem[];
    int tid = threadIdx.x;
    int m0 = blockIdx.x * 128;

    // B copy: 1536 uint4 each (256 rows x 6 uint4)
    #pragma unroll
    for (int t = 0; t < 6; t++) {
        int i = tid + t * 256;
        int r = i / 6, c = (i - r * 6) * 16;
        *(uint4*)(smem + G2_BH + r * 112 + c) = *(const uint4*)(g_B2h + r * 96 + c);
        *(uint4*)(smem + G2_BL + r * 112 + c) = *(const uint4*)(g_B2l + r * 96 + c);
    }
    // A load fp32 (g_h, padded rows valid) + split
    #pragma unroll
    for (int t = 0; t < 32; t++) {
        int i = tid + t * 256;               // 0..8191
        int r = i >> 6, kq = (i & 63) * 4;
        float4 v = *(const float4*)&g_h[(size_t)(m0 + r) * 256 + kq];
        uint2 hi, lo;
        split4(v, hi, lo);
        *(uint2*)(smem + G2_AH + (r * 264 + kq) * 2) = hi;
        *(uint2*)(smem + G2_AL + (r * 264 + kq) * 2) = lo;
    }
    __syncthreads();

    int wid = tid >> 5;                       // warp tile 16 x 48

    wmma::fragment<wmma::accumulator, 16, 16, 16, float> acc[3];
    #pragma unroll
    for (int j = 0; j < 3; j++) wmma::fill_fragment(acc[j], 0.f);

    for (int pass = 0; pass < 3; pass++) {
        const __nv_bfloat16* A_ = (const __nv_bfloat16*)(smem + (pass == 2 ? G2_AL : G2_AH));
        const __nv_bfloat16* B_ = (const __nv_bfloat16*)(smem + (pass == 1 ? G2_BL : G2_BH));
        #pragma unroll
        for (int k16 = 0; k16 < 16; k16++) {
            wmma::fragment<wmma::matrix_a, 16, 16, 16, __nv_bfloat16, wmma::row_major> af;
            wmma::fragment<wmma::matrix_b, 16, 16, 16, __nv_bfloat16, wmma::row_major> bfr[3];
            wmma::load_matrix_sync(af, A_ + (wid * 16) * 264 + k16 * 16, 264);
            #pragma unroll
            for (int j = 0; j < 3; j++)
                wmma::load_matrix_sync(bfr[j], B_ + (k16 * 16) * 56 + j * 16, 56);
            #pragma unroll
            for (int j = 0; j < 3; j++)
                wmma::mma_sync(acc[j], af, bfr[j], acc[j]);
        }
    }
    #pragma unroll
    for (int j = 0; j < 3; j++)
        wmma::store_matrix_sync(&g_Wh2[(size_t)(m0 + wid * 16) * 48 + j * 16],
                                acc[j], 48, wmma::mem_row_major);
}

// ---------------- attention scalars ----------------
__global__ void k_s1(const float* __restrict__ a) {
    int gw = (blockIdx.x * blockDim.x + threadIdx.x) >> 5;
    int lane = threadIdx.x & 31;
    if (gw >= NN) return;
    const float* wp = &g_Wh1[(size_t)gw * 256];
    float sr[4] = {0.f, 0.f, 0.f, 0.f};
    float sc[4] = {0.f, 0.f, 0.f, 0.f};
    #pragma unroll
    for (int r = 0; r < 8; r++) {
        int h = r >> 1;
        int c = (r & 1) * 32 + lane;
        float w = __ldg(&wp[r * 32 + lane]);
        sr[h] += w * __ldg(&a[h * 128 + c]);
        sc[h] += w * __ldg(&a[h * 128 + 64 + c]);
    }
    #pragma unroll
    for (int h = 0; h < 4; h++) { sr[h] = wsum(sr[h]); sc[h] = wsum(sc[h]); }
    if (lane == 0) {
        *(float4*)&g_s1r[gw * 4] = make_float4(sr[0], sr[1], sr[2], sr[3]);
        *(float4*)&g_s1c[gw * 4] = make_float4(sc[0], sc[1], sc[2], sc[3]);
    }
}

__global__ void k_s2(const float* __restrict__ aout) {
    int gw = (blockIdx.x * blockDim.x + threadIdx.x) >> 5;
    int lane = threadIdx.x & 31;
    if (gw >= NN) return;
    const float* wp = &g_Wh2[(size_t)gw * 48];
    float v0 = __ldg(&wp[lane]);
    float v1 = (lane < 8) ? __ldg(&wp[32 + lane]) : 0.f;
    float sr = v0 * __ldg(&aout[lane]) + ((lane < 8) ? v1 * __ldg(&aout[32 + lane]) : 0.f);
    float sc = v0 * __ldg(&aout[40 + lane]) + ((lane < 8) ? v1 * __ldg(&aout[72 + lane]) : 0.f);
    sr = wsum(sr); sc = wsum(sc);
    if (lane == 0) { g_s2r[gw] = sr; g_s2c[gw] = sc; }
}

// ---------------- layer1 aggregation (warp per node, float4 gathers) ----------------
__global__ void k_gat1() {
    int gw = (blockIdx.x * blockDim.x + threadIdx.x) >> 5;
    int lane = threadIdx.x & 31;
    if (gw >= NN) return;
    const float4 sr = *(const float4*)&g_s1r[gw * 4];
    int beg = g_off[gw], end = g_off[gw + 1];

    float4 acc0 = make_float4(0.f, 0.f, 0.f, 0.f);
    float4 acc1 = make_float4(0.f, 0.f, 0.f, 0.f);
    float d0 = 0.f, d1 = 0.f, d2 = 0.f, d3 = 0.f;

    for (int base = beg; base < end; base += 32) {
        int e = base + lane;
        int j = 0; float ex0 = 0.f, ex1 = 0.f, ex2 = 0.f, ex3 = 0.f;
        if (e < end) {
            j = __ldg(&g_csr[e]);
            float4 s = __ldg((const float4*)&g_s1c[j * 4]);
            ex0 = __expf(lrelu(sr.x + s.x));
            ex1 = __expf(lrelu(sr.y + s.y));
            ex2 = __expf(lrelu(sr.z + s.z));
            ex3 = __expf(lrelu(sr.w + s.w));
            d0 += ex0; d1 += ex1; d2 += ex2; d3 += ex3;
        }
        int cnt = min(32, end - base);
        for (int k = 0; k < cnt; k++) {
            int   jj = __shfl_sync(0xffffffffu, j,   k);
            float w0 = __shfl_sync(0xffffffffu, ex0, k);
            float w1 = __shfl_sync(0xffffffffu, ex1, k);
            float w2 = __shfl_sync(0xffffffffu, ex2, k);
            float w3 = __shfl_sync(0xffffffffu, ex3, k);
            const float* wp = &g_Wh1[(size_t)jj * 256];
            float4 v0 = __ldg((const float4*)&wp[4 * lane]);
            float4 v1 = __ldg((const float4*)&wp[128 + 4 * lane]);
            float wa = (lane < 16) ? w0 : w1;
            float wb = (lane < 16) ? w2 : w3;
            acc0.x += wa * v0.x; acc0.y += wa * v0.y; acc0.z += wa * v0.z; acc0.w += wa * v0.w;
            acc1.x += wb * v1.x; acc1.y += wb * v1.y; acc1.z += wb * v1.z; acc1.w += wb * v1.w;
        }
    }
    d0 = wsum(d0); d1 = wsum(d1); d2 = wsum(d2); d3 = wsum(d3);
    float inva = (lane < 16) ? (1.f / d0) : (1.f / d1);
    float invb = (lane < 16) ? (1.f / d2) : (1.f / d3);

    float* op = &g_h[(size_t)gw * 256];
    *(float4*)&op[4 * lane] = make_float4(elu(acc0.x * inva), elu(acc0.y * inva),
                                          elu(acc0.z * inva), elu(acc0.w * inva));
    *(float4*)&op[128 + 4 * lane] = make_float4(elu(acc1.x * invb), elu(acc1.y * invb),
                                                elu(acc1.z * invb), elu(acc1.w * invb));
}

// ---------------- layer2 attention + ELU + log_softmax ----------------
__global__ void k_gat2(float* __restrict__ out) {
    int gw = (blockIdx.x * blockDim.x + threadIdx.x) >> 5;
    int lane = threadIdx.x & 31;
    if (gw >= NN) return;
    float s2v = __ldg(&g_s2r[gw]);
    int beg = g_off[gw], end = g_off[gw + 1];

    float4 acc = make_float4(0.f, 0.f, 0.f, 0.f);
    float den = 0.f;
    for (int base = beg; base < end; base += 32) {
        int e = base + lane;
        int j = 0; float ex = 0.f;
        if (e < end) {
            j = __ldg(&g_csr[e]);
            ex = __expf(lrelu(s2v + __ldg(&g_s2c[j])));
            den += ex;
        }
        int cnt = min(32, end - base);
        for (int k = 0; k < cnt; k++) {
            int   jj = __shfl_sync(0xffffffffu, j,  k);
            float w  = __shfl_sync(0xffffffffu, ex, k);
            if (lane < 10) {
                float4 v = __ldg((const float4*)&g_Wh2[(size_t)jj * 48 + 4 * lane]);
                acc.x += w * v.x; acc.y += w * v.y; acc.z += w * v.z; acc.w += w * v.w;
            }
        }
    }
    den = wsum(den);
    float inv = 1.f / den;
    float o0 = -1e30f, o1 = -1e30f, o2 = -1e30f, o3 = -1e30f;
    if (lane < 10) {
        o0 = elu(acc.x * inv); o1 = elu(acc.y * inv);
        o2 = elu(acc.z * inv); o3 = elu(acc.w * inv);
    }
    float mm = wmax(fmaxf(fmaxf(o0, o1), fmaxf(o2, o3)));
    float se = 0.f;
    if (lane < 10) se = __expf(o0 - mm) + __expf(o1 - mm) + __expf(o2 - mm) + __expf(o3 - mm);
    se = wsum(se);
    float L = mm + logf(se);
    if (lane < 10)
        *(float4*)&out[(size_t)gw * NCLASS + 4 * lane] = make_float4(o0 - L, o1 - L, o2 - L, o3 - L);
}

// ---------------- launch ----------------
extern "C" void kernel_launch(void* const* d_in, const int* in_sizes, int n_in,
                              void* d_out, int out_size) {
    const float* x    = (const float*)d_in[0];
    const float* W    = (const float*)d_in[1];
    const float* a    = (const float*)d_in[2];
    const float* Wout = (const float*)d_in[3];
    const float* aout = (const float*)d_in[4];
    const int*   row  = (const int*)d_in[5];
    const int*   col  = (const int*)d_in[6];
    int E = in_sizes[5];
    float* out = (float*)d_out;

    static cudaStream_t s2 = nullptr;
    static cudaEvent_t evF = nullptr, evJ = nullptr;
    if (!s2) {
        cudaStreamCreateWithFlags(&s2, cudaStreamNonBlocking);
        cudaEventCreateWithFlags(&evF, cudaEventDisableTiming);
        cudaEventCreateWithFlags(&evJ, cudaEventDisableTiming);
        cudaFuncSetAttribute(k_gemm1, cudaFuncAttributeMaxDynamicSharedMemorySize, G1_BYTES);
        cudaFuncSetAttribute(k_gemm2, cudaFuncAttributeMaxDynamicSharedMemorySize, G2_BYTES);
    }

    k_prep<<<88, 256>>>(W, Wout);                        // 1

    // fork CSR chain onto s2
    cudaEventRecord(evF, 0);
    cudaStreamWaitEvent(s2, evF, 0);
    k_zero <<<(NN + 255) / 256, 256, 0, s2>>>();         // 2
    k_count<<<(E + 255) / 256, 256, 0, s2>>>(row, E);    // 3

    k_gemm1<<<NTILE, 256, G1_BYTES>>>(x);                // 4 (profiled slot)

    k_scan1<<<NB1, SB, 0, s2>>>();
    k_scan2<<<1, 256, 0, s2>>>();
    k_scan3<<<NB1, SB, 0, s2>>>(E);
    k_fill <<<(E + 255) / 256, 256, 0, s2>>>(row, col, E);

    k_s1<<<(NN + 7) / 8, 256>>>(a);                      // main

    // join: gat1 needs CSR (s2) and Wh1/s1 (main)
    cudaEventRecord(evJ, s2);
    cudaStreamWaitEvent(0, evJ, 0);

    k_gat1<<<(NN + 7) / 8, 256>>>();

    k_gemm2<<<NTILE, 256, G2_BYTES>>>();
    k_s2<<<(NN + 7) / 8, 256>>>(aout);
    k_gat2<<<(NN + 7) / 8, 256>>>(out);
}

// round 5
// speedup vs baseline: 1.3081x; 1.0576x over previous
#include <cuda_runtime.h>
#include <cuda_bf16.h>
#include <mma.h>
#include <math.h>
#include <stdint.h>

using namespace nvcuda;

// Problem constants
#define NN      100000
#define EMAX    1700000
#define NCLASS  40
#define SB      512
#define NB1     ((NN + SB - 1) / SB)
#define NTILE   782                    // ceil(NN/128)
#define NPAD    (NTILE * 128)          // 100096

// ---------------- scratch (static device globals) ----------------
__device__ float g_Wh1[(size_t)NPAD * 256];   // layer1 Wh fp32
__device__ float g_Wh2[(size_t)NPAD * 48];    // layer2 Wh fp32, ld=48 (cols 40..47 zero)
__device__ float g_s1r[NN * 4];
__device__ float g_s1c[NN * 4];
__device__ float g_s2r[NN];
__device__ float g_s2c[NN];
__device__ int   g_deg[NN];
__device__ int   g_cur[NN];
__device__ int   g_off[NN + 1];
__device__ int   g_csr[EMAX];
__device__ int   g_bsum[256];
__device__ int   g_boff[256];
// pre-split bf16 operands (row-major)
__device__ __align__(16) unsigned char g_xh[(size_t)NPAD * 128 * 2];  // x hi  [N][128]
__device__ __align__(16) unsigned char g_xl[(size_t)NPAD * 128 * 2];  // x lo
__device__ __align__(16) unsigned char g_hh[(size_t)NPAD * 256 * 2];  // h hi  [N][256]
__device__ __align__(16) unsigned char g_hl[(size_t)NPAD * 256 * 2];  // h lo
__device__ __align__(16) unsigned char g_B1h[128 * 256 * 2];          // B1[k][n] ld 256
__device__ __align__(16) unsigned char g_B1l[128 * 256 * 2];
__device__ __align__(16) unsigned char g_B2h[256 * 48 * 2];           // B2[k][n] ld 48
__device__ __align__(16) unsigned char g_B2l[256 * 48 * 2];

// ---------------- helpers ----------------
__device__ __forceinline__ uint32_t smem_u32(const void* p) {
    uint32_t a;
    asm("{ .reg .u64 t; cvta.to.shared.u64 t, %1; cvt.u32.u64 %0, t; }" : "=r"(a) : "l"(p));
    return a;
}
__device__ __forceinline__ void cpa16(uint32_t dst, const void* src) {
    asm volatile("cp.async.cg.shared.global [%0], [%1], 16;" :: "r"(dst), "l"(src));
}
#define CP_COMMIT() asm volatile("cp.async.commit_group;" ::: "memory")
#define CP_WAIT1()  asm volatile("cp.async.wait_group 1;" ::: "memory")
#define CP_WAIT0()  asm volatile("cp.async.wait_group 0;" ::: "memory")

__device__ __forceinline__ float wmax(float v) {
    #pragma unroll
    for (int o = 16; o; o >>= 1) v = fmaxf(v, __shfl_xor_sync(0xffffffffu, v, o));
    return v;
}
__device__ __forceinline__ float wsum(float v) {
    #pragma unroll
    for (int o = 16; o; o >>= 1) v += __shfl_xor_sync(0xffffffffu, v, o);
    return v;
}
__device__ __forceinline__ float lrelu(float v) { return v > 0.f ? v : 0.1f * v; }
__device__ __forceinline__ float elu(float v)   { return v > 0.f ? v : expm1f(v); }

__device__ __forceinline__ void split4(float4 v, uint2& hi, uint2& lo) {
    __nv_bfloat16 h0 = __float2bfloat16_rn(v.x), h1 = __float2bfloat16_rn(v.y),
                  h2 = __float2bfloat16_rn(v.z), h3 = __float2bfloat16_rn(v.w);
    hi.x = ((uint32_t)__bfloat16_as_ushort(h1) << 16) | __bfloat16_as_ushort(h0);
    hi.y = ((uint32_t)__bfloat16_as_ushort(h3) << 16) | __bfloat16_as_ushort(h2);
    __nv_bfloat162 l01 = __floats2bfloat162_rn(v.x - __bfloat162float(h0), v.y - __bfloat162float(h1));
    __nv_bfloat162 l23 = __floats2bfloat162_rn(v.z - __bfloat162float(h2), v.w - __bfloat162float(h3));
    lo.x = *(uint32_t*)&l01;
    lo.y = *(uint32_t*)&l23;
}

// ---------------- prep: split x and weights to bf16 hi/lo ----------------
#define XIT 3200000   // NN*128/4 float4 items
__global__ void k_prep(const float* __restrict__ x, const float* __restrict__ W,
                       const float* __restrict__ Wout) {
    int stride = gridDim.x * blockDim.x;
    for (int i = blockIdx.x * blockDim.x + threadIdx.x; i < XIT + 32768 + 12288 + 6144; i += stride) {
        if (i < XIT) {                          // x split
            int r = i >> 5, kq = (i & 31) * 4;
            float4 v = __ldg((const float4*)&x[(size_t)r * 128 + kq]);
            uint2 hi, lo;
            split4(v, hi, lo);
            *(uint2*)(g_xh + ((size_t)r * 128 + kq) * 2) = hi;
            *(uint2*)(g_xl + ((size_t)r * 128 + kq) * 2) = lo;
        } else if (i < XIT + 32768) {           // B1[k][n] = W[n/64][k][n%64]
            int i2 = i - XIT;
            int k = i2 >> 8, n = i2 & 255;
            float v = W[(n >> 6) * 8192 + k * 64 + (n & 63)];
            __nv_bfloat16 h = __float2bfloat16_rn(v);
            __nv_bfloat16 l = __float2bfloat16_rn(v - __bfloat162float(h));
            *(__nv_bfloat16*)(g_B1h + (size_t)i2 * 2) = h;
            *(__nv_bfloat16*)(g_B1l + (size_t)i2 * 2) = l;
        } else if (i < XIT + 32768 + 12288) {   // B2[k][n] = Wout[k][n] (n<40 else 0)
            int j = i - XIT - 32768;
            int k = j / 48, n = j - k * 48;
            float v = (n < NCLASS) ? Wout[k * NCLASS + n] : 0.f;
            __nv_bfloat16 h = __float2bfloat16_rn(v);
            __nv_bfloat16 l = __float2bfloat16_rn(v - __bfloat162float(h));
            *(__nv_bfloat16*)(g_B2h + (size_t)j * 2) = h;
            *(__nv_bfloat16*)(g_B2l + (size_t)j * 2) = l;
        } else {                                // zero h pad rows (NN..NPAD)
            int j = i - XIT - 45056;
            uint4 z = make_uint4(0, 0, 0, 0);
            if (j < 3072) *(uint4*)(g_hh + (size_t)NN * 512 + (size_t)j * 16) = z;
            else          *(uint4*)(g_hl + (size_t)NN * 512 + (size_t)(j - 3072) * 16) = z;
        }
    }
}

// ---------------- CSR build ----------------
__global__ void k_zero() {
    int i = blockIdx.x * blockDim.x + threadIdx.x;
    if (i < NN) { g_deg[i] = 0; g_cur[i] = 0; }
}
__global__ void k_count(const int* __restrict__ row, int E) {
    int e = blockIdx.x * blockDim.x + threadIdx.x;
    if (e < E) atomicAdd(&g_deg[__ldg(&row[e])], 1);
}
__global__ void k_scan1() {
    __shared__ int s[SB];
    int tid = threadIdx.x, g = blockIdx.x * SB + tid;
    int v = (g < NN) ? g_deg[g] : 0;
    s[tid] = v; __syncthreads();
    for (int o = 1; o < SB; o <<= 1) {
        int t = (tid >= o) ? s[tid - o] : 0;
        __syncthreads(); s[tid] += t; __syncthreads();
    }
    if (g < NN) g_off[g] = s[tid] - v;
    if (tid == SB - 1) g_bsum[blockIdx.x] = s[tid];
}
__global__ void k_scan2() {
    __shared__ int s[256];
    int tid = threadIdx.x;
    int v = (tid < NB1) ? g_bsum[tid] : 0;
    s[tid] = v; __syncthreads();
    for (int o = 1; o < 256; o <<= 1) {
        int t = (tid >= o) ? s[tid - o] : 0;
        __syncthreads(); s[tid] += t; __syncthreads();
    }
    g_boff[tid] = s[tid] - v;
}
__global__ void k_scan3(int E) {
    int tid = threadIdx.x, g = blockIdx.x * SB + tid;
    if (g < NN) g_off[g] += g_boff[blockIdx.x];
    if (g == 0) g_off[NN] = E;
}
__global__ void k_fill(const int* __restrict__ row, const int* __restrict__ col, int E) {
    int e = blockIdx.x * blockDim.x + threadIdx.x;
    if (e >= E) return;
    int r = __ldg(&row[e]);
    int p = g_off[r] + atomicAdd(&g_cur[r], 1);
    g_csr[p] = __ldg(&col[e]);
}

// ---------------- GEMM1: Wh1 = x @ B1  [128x256 tile, K=128, 2 k-chunks pipelined] ----------------
#define S1_AH 0
#define S1_AL 18432
#define S1_BH 36864
#define S1_BL 70656
#define S1_STAGE 104448
#define S1_BYTES (2 * S1_STAGE)

__global__ __launch_bounds__(256) void k_gemm1() {
    extern __shared__ __align__(16) unsigned char smem[];
    uint32_t sbase = smem_u32(smem);
    int tid = threadIdx.x;
    int m0 = blockIdx.x * 128;

    // issue cp.async for both k-chunks (2 commit groups)
    #pragma unroll
    for (int c = 0; c < 2; c++) {
        uint32_t st = sbase + c * S1_STAGE;
        #pragma unroll
        for (int t = 0; t < 4; t++) {           // A: 1024 chunks/buffer
            int idx = tid + t * 256;
            int r = idx >> 3, c8 = idx & 7;
            size_t so = ((size_t)(m0 + r) * 128 + c * 64 + c8 * 8) * 2;
            uint32_t doff = (uint32_t)(r * 72 + c8 * 8) * 2;
            cpa16(st + S1_AH + doff, g_xh + so);
            cpa16(st + S1_AL + doff, g_xl + so);
        }
        #pragma unroll
        for (int t = 0; t < 8; t++) {           // B: 2048 chunks/buffer
            int idx = tid + t * 256;
            int kr = idx >> 5, c16 = idx & 31;
            size_t so = ((size_t)(c * 64 + kr) * 256 + c16 * 8) * 2;
            uint32_t doff = (uint32_t)(kr * 264 + c16 * 8) * 2;
            cpa16(st + S1_BH + doff, g_B1h + so);
            cpa16(st + S1_BL + doff, g_B1l + so);
        }
        CP_COMMIT();
    }

    int wid = tid >> 5, wm = wid & 1, wn = wid >> 1;  // 2 M x 4 N warps, tile 64x64

    wmma::fragment<wmma::accumulator, 16, 16, 16, float> acc[4][4];
    #pragma unroll
    for (int i = 0; i < 4; i++)
        #pragma unroll
        for (int j = 0; j < 4; j++) wmma::fill_fragment(acc[i][j], 0.f);

    CP_WAIT1();
    __syncthreads();

    #pragma unroll
    for (int c = 0; c < 2; c++) {
        const unsigned char* st = smem + c * S1_STAGE;
        #pragma unroll
        for (int pass = 0; pass < 3; pass++) {
            const __nv_bfloat16* A_ = (const __nv_bfloat16*)(st + (pass == 2 ? S1_AL : S1_AH));
            const __nv_bfloat16* B_ = (const __nv_bfloat16*)(st + (pass == 1 ? S1_BL : S1_BH));
            #pragma unroll
            for (int k8 = 0; k8 < 4; k8++) {
                wmma::fragment<wmma::matrix_a, 16, 16, 16, __nv_bfloat16, wmma::row_major> af[4];
                wmma::fragment<wmma::matrix_b, 16, 16, 16, __nv_bfloat16, wmma::row_major> bfr[4];
                #pragma unroll
                for (int i = 0; i < 4; i++)
                    wmma::load_matrix_sync(af[i], A_ + (wm * 64 + i * 16) * 72 + k8 * 16, 72);
                #pragma unroll
                for (int j = 0; j < 4; j++)
                    wmma::load_matrix_sync(bfr[j], B_ + (k8 * 16) * 264 + wn * 64 + j * 16, 264);
                #pragma unroll
                for (int i = 0; i < 4; i++)
                    #pragma unroll
                    for (int j = 0; j < 4; j++)
                        wmma::mma_sync(acc[i][j], af[i], bfr[j], acc[i][j]);
            }
        }
        if (c == 0) { CP_WAIT0(); __syncthreads(); }
    }

    #pragma unroll
    for (int i = 0; i < 4; i++)
        #pragma unroll
        for (int j = 0; j < 4; j++)
            wmma::store_matrix_sync(&g_Wh1[(size_t)(m0 + wm * 64 + i * 16) * 256 + wn * 64 + j * 16],
                                    acc[i][j], 256, wmma::mem_row_major);
}

// ---------------- GEMM2: Wh2 = h @ B2  [128x48 tile, K=256, 2 k-chunks pipelined] ----------------
#define S2_AH 0
#define S2_AL 34816
#define S2_BH 69632
#define S2_BL 83968
#define S2_STAGE 98304
#define S2_BYTES (2 * S2_STAGE)

__global__ __launch_bounds__(256) void k_gemm2() {
    extern __shared__ __align__(16) unsigned char smem[];
    uint32_t sbase = smem_u32(smem);
    int tid = threadIdx.x;
    int m0 = blockIdx.x * 128;

    #pragma unroll
    for (int c = 0; c < 2; c++) {
        uint32_t st = sbase + c * S2_STAGE;
        #pragma unroll
        for (int t = 0; t < 8; t++) {           // A: 2048 chunks/buffer
            int idx = tid + t * 256;
            int r = idx >> 4, c16 = idx & 15;
            size_t so = ((size_t)(m0 + r) * 256 + c * 128 + c16 * 8) * 2;
            uint32_t doff = (uint32_t)(r * 136 + c16 * 8) * 2;
            cpa16(st + S2_AH + doff, g_hh + so);
            cpa16(st + S2_AL + doff, g_hl + so);
        }
        #pragma unroll
        for (int t = 0; t < 3; t++) {           // B: 768 chunks/buffer
            int idx = tid + t * 256;
            int kr = idx / 6, c6 = idx - kr * 6;
            size_t so = ((size_t)(c * 128 + kr) * 48 + c6 * 8) * 2;
            uint32_t doff = (uint32_t)(kr * 56 + c6 * 8) * 2;
            cpa16(st + S2_BH + doff, g_B2h + so);
            cpa16(st + S2_BL + doff, g_B2l + so);
        }
        CP_COMMIT();
    }

    int wid = tid >> 5;                          // warp tile 16 x 48

    wmma::fragment<wmma::accumulator, 16, 16, 16, float> acc[3];
    #pragma unroll
    for (int j = 0; j < 3; j++) wmma::fill_fragment(acc[j], 0.f);

    CP_WAIT1();
    __syncthreads();

    #pragma unroll
    for (int c = 0; c < 2; c++) {
        const unsigned char* st = smem + c * S2_STAGE;
        #pragma unroll
        for (int pass = 0; pass < 3; pass++) {
            const __nv_bfloat16* A_ = (const __nv_bfloat16*)(st + (pass == 2 ? S2_AL : S2_AH));
            const __nv_bfloat16* B_ = (const __nv_bfloat16*)(st + (pass == 1 ? S2_BL : S2_BH));
            #pragma unroll
            for (int k16 = 0; k16 < 8; k16++) {
                wmma::fragment<wmma::matrix_a, 16, 16, 16, __nv_bfloat16, wmma::row_major> af;
                wmma::fragment<wmma::matrix_b, 16, 16, 16, __nv_bfloat16, wmma::row_major> bfr[3];
                wmma::load_matrix_sync(af, A_ + (wid * 16) * 136 + k16 * 16, 136);
                #pragma unroll
                for (int j = 0; j < 3; j++)
                    wmma::load_matrix_sync(bfr[j], B_ + (k16 * 16) * 56 + j * 16, 56);
                #pragma unroll
                for (int j = 0; j < 3; j++)
                    wmma::mma_sync(acc[j], af, bfr[j], acc[j]);
            }
        }
        if (c == 0) { CP_WAIT0(); __syncthreads(); }
    }

    #pragma unroll
    for (int j = 0; j < 3; j++)
        wmma::store_matrix_sync(&g_Wh2[(size_t)(m0 + wid * 16) * 48 + j * 16],
                                acc[j], 48, wmma::mem_row_major);
}

// ---------------- attention scalars ----------------
__global__ void k_s1(const float* __restrict__ a) {
    int gw = (blockIdx.x * blockDim.x + threadIdx.x) >> 5;
    int lane = threadIdx.x & 31;
    if (gw >= NN) return;
    const float* wp = &g_Wh1[(size_t)gw * 256];
    float sr[4] = {0.f, 0.f, 0.f, 0.f};
    float sc[4] = {0.f, 0.f, 0.f, 0.f};
    #pragma unroll
    for (int r = 0; r < 8; r++) {
        int h = r >> 1;
        int c = (r & 1) * 32 + lane;
        float w = __ldg(&wp[r * 32 + lane]);
        sr[h] += w * __ldg(&a[h * 128 + c]);
        sc[h] += w * __ldg(&a[h * 128 + 64 + c]);
    }
    #pragma unroll
    for (int h = 0; h < 4; h++) { sr[h] = wsum(sr[h]); sc[h] = wsum(sc[h]); }
    if (lane == 0) {
        *(float4*)&g_s1r[gw * 4] = make_float4(sr[0], sr[1], sr[2], sr[3]);
        *(float4*)&g_s1c[gw * 4] = make_float4(sc[0], sc[1], sc[2], sc[3]);
    }
}

__global__ void k_s2(const float* __restrict__ aout) {
    int gw = (blockIdx.x * blockDim.x + threadIdx.x) >> 5;
    int lane = threadIdx.x & 31;
    if (gw >= NN) return;
    const float* wp = &g_Wh2[(size_t)gw * 48];
    float v0 = __ldg(&wp[lane]);
    float v1 = (lane < 8) ? __ldg(&wp[32 + lane]) : 0.f;
    float sr = v0 * __ldg(&aout[lane]) + ((lane < 8) ? v1 * __ldg(&aout[32 + lane]) : 0.f);
    float sc = v0 * __ldg(&aout[40 + lane]) + ((lane < 8) ? v1 * __ldg(&aout[72 + lane]) : 0.f);
    sr = wsum(sr); sc = wsum(sc);
    if (lane == 0) { g_s2r[gw] = sr; g_s2c[gw] = sc; }
}

// ---------------- layer1 aggregation (warp per node); emits h as bf16 hi/lo ----------------
__global__ void k_gat1() {
    int gw = (blockIdx.x * blockDim.x + threadIdx.x) >> 5;
    int lane = threadIdx.x & 31;
    if (gw >= NN) return;
    const float4 sr = *(const float4*)&g_s1r[gw * 4];
    int beg = g_off[gw], end = g_off[gw + 1];

    float4 acc0 = make_float4(0.f, 0.f, 0.f, 0.f);
    float4 acc1 = make_float4(0.f, 0.f, 0.f, 0.f);
    float d0 = 0.f, d1 = 0.f, d2 = 0.f, d3 = 0.f;

    for (int base = beg; base < end; base += 32) {
        int e = base + lane;
        int j = 0; float ex0 = 0.f, ex1 = 0.f, ex2 = 0.f, ex3 = 0.f;
        if (e < end) {
            j = __ldg(&g_csr[e]);
            float4 s = __ldg((const float4*)&g_s1c[j * 4]);
            ex0 = __expf(lrelu(sr.x + s.x));
            ex1 = __expf(lrelu(sr.y + s.y));
            ex2 = __expf(lrelu(sr.z + s.z));
            ex3 = __expf(lrelu(sr.w + s.w));
            d0 += ex0; d1 += ex1; d2 += ex2; d3 += ex3;
        }
        int cnt = min(32, end - base);
        for (int k = 0; k < cnt; k++) {
            int   jj = __shfl_sync(0xffffffffu, j,   k);
            float w0 = __shfl_sync(0xffffffffu, ex0, k);
            float w1 = __shfl_sync(0xffffffffu, ex1, k);
            float w2 = __shfl_sync(0xffffffffu, ex2, k);
            float w3 = __shfl_sync(0xffffffffu, ex3, k);
            const float* wp = &g_Wh1[(size_t)jj * 256];
            float4 v0 = __ldg((const float4*)&wp[4 * lane]);
            float4 v1 = __ldg((const float4*)&wp[128 + 4 * lane]);
            float wa = (lane < 16) ? w0 : w1;
            float wb = (lane < 16) ? w2 : w3;
            acc0.x += wa * v0.x; acc0.y += wa * v0.y; acc0.z += wa * v0.z; acc0.w += wa * v0.w;
            acc1.x += wb * v1.x; acc1.y += wb * v1.y; acc1.z += wb * v1.z; acc1.w += wb * v1.w;
        }
    }
    d0 = wsum(d0); d1 = wsum(d1); d2 = wsum(d2); d3 = wsum(d3);
    float inva = (lane < 16) ? (1.f / d0) : (1.f / d1);
    float invb = (lane < 16) ? (1.f / d2) : (1.f / d3);

    float4 r0 = make_float4(elu(acc0.x * inva), elu(acc0.y * inva),
                            elu(acc0.z * inva), elu(acc0.w * inva));
    float4 r1 = make_float4(elu(acc1.x * invb), elu(acc1.y * invb),
                            elu(acc1.z * invb), elu(acc1.w * invb));
    uint2 h0, l0, h1, l1;
    split4(r0, h0, l0);
    split4(r1, h1, l1);
    size_t o0 = ((size_t)gw * 256 + 4 * lane) * 2;
    size_t o1 = ((size_t)gw * 256 + 128 + 4 * lane) * 2;
    *(uint2*)(g_hh + o0) = h0;
    *(uint2*)(g_hl + o0) = l0;
    *(uint2*)(g_hh + o1) = h1;
    *(uint2*)(g_hl + o1) = l1;
}

// ---------------- layer2 attention + ELU + log_softmax (2 edges per step) ----------------
__global__ void k_gat2(float* __restrict__ out) {
    int gw = (blockIdx.x * blockDim.x + threadIdx.x) >> 5;
    int lane = threadIdx.x & 31;
    if (gw >= NN) return;
    float s2v = __ldg(&g_s2r[gw]);
    int beg = g_off[gw], end = g_off[gw + 1];
    int half = lane >> 4, sl = lane & 15;

    float4 acc = make_float4(0.f, 0.f, 0.f, 0.f);
    float den = 0.f;
    for (int base = beg; base < end; base += 32) {
        int e = base + lane;
        int j = 0; float ex = 0.f;
        if (e < end) {
            j = __ldg(&g_csr[e]);
            ex = __expf(lrelu(s2v + __ldg(&g_s2c[j])));
            den += ex;
        }
        int cnt = min(32, end - base);
        for (int k = 0; k < cnt; k += 2) {
            int kk = k + half;
            int src = (kk < cnt) ? kk : k;
            int   jj = __shfl_sync(0xffffffffu, j,  src);
            float w  = __shfl_sync(0xffffffffu, ex, src);
            if (kk >= cnt) w = 0.f;
            if (sl < 10) {
                float4 v = __ldg((const float4*)&g_Wh2[(size_t)jj * 48 + 4 * sl]);
                acc.x += w * v.x; acc.y += w * v.y; acc.z += w * v.z; acc.w += w * v.w;
            }
        }
    }
    // combine half-warps
    acc.x += __shfl_xor_sync(0xffffffffu, acc.x, 16);
    acc.y += __shfl_xor_sync(0xffffffffu, acc.y, 16);
    acc.z += __shfl_xor_sync(0xffffffffu, acc.z, 16);
    acc.w += __shfl_xor_sync(0xffffffffu, acc.w, 16);
    den = wsum(den);
    float inv = 1.f / den;
    bool valid = (lane < 10);
    float o0 = -1e30f, o1 = -1e30f, o2 = -1e30f, o3 = -1e30f;
    if (valid) {
        o0 = elu(acc.x * inv); o1 = elu(acc.y * inv);
        o2 = elu(acc.z * inv); o3 = elu(acc.w * inv);
    }
    float mm = wmax(fmaxf(fmaxf(o0, o1), fmaxf(o2, o3)));
    float se = 0.f;
    if (valid) se = __expf(o0 - mm) + __expf(o1 - mm) + __expf(o2 - mm) + __expf(o3 - mm);
    se = wsum(se);
    float L = mm + logf(se);
    if (valid)
        *(float4*)&out[(size_t)gw * NCLASS + 4 * lane] = make_float4(o0 - L, o1 - L, o2 - L, o3 - L);
}

// ---------------- launch ----------------
extern "C" void kernel_launch(void* const* d_in, const int* in_sizes, int n_in,
                              void* d_out, int out_size) {
    const float* x    = (const float*)d_in[0];
    const float* W    = (const float*)d_in[1];
    const float* a    = (const float*)d_in[2];
    const float* Wout = (const float*)d_in[3];
    const float* aout = (const float*)d_in[4];
    const int*   row  = (const int*)d_in[5];
    const int*   col  = (const int*)d_in[6];
    int E = in_sizes[5];
    float* out = (float*)d_out;

    static cudaStream_t s2 = nullptr;
    static cudaEvent_t evF = nullptr, evJ = nullptr;
    if (!s2) {
        cudaStreamCreateWithFlags(&s2, cudaStreamNonBlocking);
        cudaEventCreateWithFlags(&evF, cudaEventDisableTiming);
        cudaEventCreateWithFlags(&evJ, cudaEventDisableTiming);
        cudaFuncSetAttribute(k_gemm1, cudaFuncAttributeMaxDynamicSharedMemorySize, S1_BYTES);
        cudaFuncSetAttribute(k_gemm2, cudaFuncAttributeMaxDynamicSharedMemorySize, S2_BYTES);
    }

    // fork CSR chain immediately (independent of prep)
    cudaEventRecord(evF, 0);
    cudaStreamWaitEvent(s2, evF, 0);
    k_zero <<<(NN + 255) / 256, 256, 0, s2>>>();           // 1
    k_count<<<(E + 255) / 256, 256, 0, s2>>>(row, E);      // 2

    k_prep<<<1280, 256>>>(x, W, Wout);                     // 3 (main)
    k_gemm1<<<NTILE, 256, S1_BYTES>>>();                   // 4 (profiled slot)

    k_scan1<<<NB1, SB, 0, s2>>>();
    k_scan2<<<1, 256, 0, s2>>>();
    k_scan3<<<NB1, SB, 0, s2>>>(E);
    k_fill <<<(E + 255) / 256, 256, 0, s2>>>(row, col, E);

    k_s1<<<(NN + 7) / 8, 256>>>(a);                        // main

    cudaEventRecord(evJ, s2);
    cudaStreamWaitEvent(0, evJ, 0);

    k_gat1<<<(NN + 7) / 8, 256>>>();
    k_gemm2<<<NTILE, 256, S2_BYTES>>>();
    k_s2<<<(NN + 7) / 8, 256>>>(aout);
    k_gat2<<<(NN + 7) / 8, 256>>>(out);
}